// round 1
// baseline (speedup 1.0000x reference)
#include <cuda_runtime.h>

#define DIM 256
#define KSZ 8
#define MAXC 2048   // headroom; actual C = 1024

// Scratch (no allocations allowed in kernel_launch)
__device__ float g_centers[MAXC * DIM];  // per-class (unnormalized) centers
__device__ float g_sq[MAXC];             // ||center_c||^2
__device__ float g_pc[MAXC];             // per-class sum of dist_pc over its K rows
__device__ float g_an[MAXC];             // per-class hinge sum over other classes

// ---------------------------------------------------------------------------
// Kernel 1: one block per class (K=8 rows). 256 threads = 8 warps.
//   warp w owns row w: computes row norm.
//   thread t owns dim t: computes center_d, ||center||^2, normalized center.
//   warp w then computes dot(x_w, center_normalized) -> dist_pc via 2-2*dot.
// ---------------------------------------------------------------------------
__global__ void __launch_bounds__(256) centers_kernel(const float* __restrict__ in) {
    int c    = blockIdx.x;
    int tid  = threadIdx.x;
    int w    = tid >> 5;
    int lane = tid & 31;

    __shared__ float raw[KSZ][DIM];   // raw input rows for this class
    __shared__ float invn[KSZ];       // 1/||row||
    __shared__ float cen[DIM];        // class center (unnormalized)
    __shared__ float redA[KSZ];
    __shared__ float redB[KSZ];

    const float* rowp = in + (size_t)(c * KSZ + w) * DIM;

    float v[8];
    float ss = 0.f;
#pragma unroll
    for (int j = 0; j < 8; j++) {
        float x = rowp[lane + 32 * j];
        v[j] = x;
        raw[w][lane + 32 * j] = x;
        ss += x * x;
    }
#pragma unroll
    for (int o = 16; o > 0; o >>= 1) ss += __shfl_xor_sync(0xffffffffu, ss, o);
    if (lane == 0) invn[w] = rsqrtf(ss);
    __syncthreads();

    // center_d = (1/8) * sum_k raw[k][d] * invn[k]
    float cd = 0.f;
#pragma unroll
    for (int k = 0; k < 8; k++) cd += raw[k][tid] * invn[k];
    cd *= 0.125f;
    cen[tid] = cd;
    g_centers[(size_t)c * DIM + tid] = cd;

    // ||center||^2 block reduce
    float s2 = cd * cd;
#pragma unroll
    for (int o = 16; o > 0; o >>= 1) s2 += __shfl_xor_sync(0xffffffffu, s2, o);
    if (lane == 0) redA[w] = s2;
    __syncthreads();

    float sqc = 0.f;
#pragma unroll
    for (int k = 0; k < 8; k++) sqc += redA[k];
    if (tid == 0) { g_sq[c] = sqc; g_an[c] = 0.f; }
    float icn = rsqrtf(sqc);

    // dot(x_w, cn) = invn[w] * icn * sum_d raw[w][d]*cen[d]
    float dot = 0.f;
#pragma unroll
    for (int j = 0; j < 8; j++) dot += v[j] * cen[lane + 32 * j];
#pragma unroll
    for (int o = 16; o > 0; o >>= 1) dot += __shfl_xor_sync(0xffffffffu, dot, o);
    if (lane == 0) {
        float d = invn[w] * icn * dot;
        redB[w] = sqrtf(fmaxf(2.f - 2.f * d, 0.f));   // ||x - cn|| for unit vectors
    }
    __syncthreads();
    if (tid == 0) {
        float p = 0.f;
#pragma unroll
        for (int k = 0; k < 8; k++) p += redB[k];
        g_pc[c] = p;
    }
}

// ---------------------------------------------------------------------------
// Kernel 2: tiled fp32 "GEMM" G = Cc @ Cc^T with fused hinge epilogue.
// 64x64 tile per block, 256 threads (16x16), 4x4 micro-tile per thread.
//   d2 = sq[i] + sq[j] - 2*G[i][j]; h = max(0.7 - sqrt(max(d2,1e-12)), 0)
//   row-sum over j != i  -> atomicAdd into g_an[i]
// ---------------------------------------------------------------------------
__global__ void __launch_bounds__(256) gemm_hinge(int C) {
    __shared__ __align__(16) float As[64][68];   // [k][m], padded
    __shared__ __align__(16) float Bs[64][68];   // [k][n], padded

    int tid = threadIdx.x;
    int tx  = tid & 15;
    int ty  = tid >> 4;
    int i0  = blockIdx.y * 64;
    int j0  = blockIdx.x * 64;

    float acc[4][4] = {};

    for (int kc = 0; kc < DIM; kc += 64) {
#pragma unroll
        for (int v = 0; v < 4; v++) {
            int idx = tid + v * 256;      // 0..1023
            int m   = idx >> 4;           // row within tile
            int kq  = idx & 15;           // float4 slot along k
            float4 a4 = *(const float4*)(g_centers + (size_t)(i0 + m) * DIM + kc + kq * 4);
            As[kq * 4 + 0][m] = a4.x;
            As[kq * 4 + 1][m] = a4.y;
            As[kq * 4 + 2][m] = a4.z;
            As[kq * 4 + 3][m] = a4.w;
            float4 b4 = *(const float4*)(g_centers + (size_t)(j0 + m) * DIM + kc + kq * 4);
            Bs[kq * 4 + 0][m] = b4.x;
            Bs[kq * 4 + 1][m] = b4.y;
            Bs[kq * 4 + 2][m] = b4.z;
            Bs[kq * 4 + 3][m] = b4.w;
        }
        __syncthreads();

#pragma unroll 16
        for (int kk = 0; kk < 64; kk++) {
            float4 a = *(const float4*)&As[kk][ty * 4];
            float4 b = *(const float4*)&Bs[kk][tx * 4];
            float ar[4] = {a.x, a.y, a.z, a.w};
            float br[4] = {b.x, b.y, b.z, b.w};
#pragma unroll
            for (int r = 0; r < 4; r++)
#pragma unroll
                for (int cc = 0; cc < 4; cc++)
                    acc[r][cc] = fmaf(ar[r], br[cc], acc[r][cc]);
        }
        __syncthreads();
    }

    // Fused hinge epilogue
    float sqi[4], sqj[4];
#pragma unroll
    for (int r = 0; r < 4; r++)  sqi[r]  = g_sq[i0 + ty * 4 + r];
#pragma unroll
    for (int cc = 0; cc < 4; cc++) sqj[cc] = g_sq[j0 + tx * 4 + cc];

    float rowsum[4] = {0.f, 0.f, 0.f, 0.f};
#pragma unroll
    for (int r = 0; r < 4; r++) {
        int i = i0 + ty * 4 + r;
#pragma unroll
        for (int cc = 0; cc < 4; cc++) {
            int j = j0 + tx * 4 + cc;
            float d2 = sqi[r] + sqj[cc] - 2.f * acc[r][cc];
            float d  = sqrtf(fmaxf(d2, 1e-12f));
            float h  = fmaxf(0.7f - d, 0.f);
            if (i != j) rowsum[r] += h;
        }
    }

    // reduce across the 16 threads sharing a row group (xor stays in 16-lane half)
#pragma unroll
    for (int r = 0; r < 4; r++) {
#pragma unroll
        for (int o = 1; o < 16; o <<= 1)
            rowsum[r] += __shfl_xor_sync(0xffffffffu, rowsum[r], o);
    }
    if (tx == 0) {
#pragma unroll
        for (int r = 0; r < 4; r++)
            atomicAdd(&g_an[i0 + ty * 4 + r], rowsum[r]);
    }
}

// ---------------------------------------------------------------------------
// Kernel 3: final reductions + 3 scalar outputs
// ---------------------------------------------------------------------------
__global__ void __launch_bounds__(256) finalize_kernel(float* __restrict__ out, int n, int C) {
    int tid  = threadIdx.x;
    int w    = tid >> 5;
    int lane = tid & 31;
    __shared__ float sp[8], sa[8];

    float p = 0.f, a = 0.f;
    for (int i = tid; i < C; i += 256) { p += g_pc[i]; a += g_an[i]; }
#pragma unroll
    for (int o = 16; o > 0; o >>= 1) {
        p += __shfl_xor_sync(0xffffffffu, p, o);
        a += __shfl_xor_sync(0xffffffffu, a, o);
    }
    if (lane == 0) { sp[w] = p; sa[w] = a; }
    __syncthreads();
    if (tid == 0) {
        float P = 0.f, A = 0.f;
#pragma unroll
        for (int k = 0; k < 8; k++) { P += sp[k]; A += sa[k]; }
        float pc_mean = P / (float)n;
        float an_mean = A / ((float)(C - 1) * (float)C);
        out[0] = pc_mean + an_mean;
        out[1] = pc_mean;
        out[2] = an_mean;
    }
}

extern "C" void kernel_launch(void* const* d_in, const int* in_sizes, int n_in,
                              void* d_out, int out_size) {
    const float* in = (const float*)d_in[0];
    int n = in_sizes[0] / DIM;   // 8192
    int C = n / KSZ;             // 1024

    centers_kernel<<<C, 256>>>(in);
    dim3 grid(C / 64, C / 64);
    gemm_hinge<<<grid, 256>>>(C);
    finalize_kernel<<<1, 256>>>((float*)d_out, n, C);
}

// round 2
// speedup vs baseline: 1.4458x; 1.4458x over previous
#include <cuda_runtime.h>
#include <cuda_bf16.h>
#include <cstdint>

#define DIM 256
#define KSZ 8
#define MAXC 2048   // headroom; actual C = 1024

// Scratch (no allocations allowed)
__device__ float g_sq[MAXC];                     // ||center_c||^2
__device__ float g_pc[MAXC];                     // per-class sum of dist_pc
__device__ float g_an[MAXC];                     // per-class hinge sum
__device__ __nv_bfloat16 g_hi[MAXC * DIM];       // center hi bf16
__device__ __nv_bfloat16 g_lo[MAXC * DIM];       // center lo bf16 (residual)

// ---------------------------------------------------------------------------
// Kernel 1: one block per class (K=8 rows). 256 threads = 8 warps.
// Computes normalized rows, class center, ||center||^2, dist_pc, and
// the hi/lo bf16 split of the center for the tensor-core Gram GEMM.
// ---------------------------------------------------------------------------
__global__ void __launch_bounds__(256) centers_kernel(const float* __restrict__ in) {
    int c    = blockIdx.x;
    int tid  = threadIdx.x;
    int w    = tid >> 5;
    int lane = tid & 31;

    __shared__ float raw[KSZ][DIM];
    __shared__ float invn[KSZ];
    __shared__ float cen[DIM];
    __shared__ float redA[KSZ];
    __shared__ float redB[KSZ];

    const float* rowp = in + (size_t)(c * KSZ + w) * DIM;

    float v[8];
    float ss = 0.f;
#pragma unroll
    for (int j = 0; j < 8; j++) {
        float x = rowp[lane + 32 * j];
        v[j] = x;
        raw[w][lane + 32 * j] = x;
        ss += x * x;
    }
#pragma unroll
    for (int o = 16; o > 0; o >>= 1) ss += __shfl_xor_sync(0xffffffffu, ss, o);
    if (lane == 0) invn[w] = rsqrtf(ss);
    __syncthreads();

    // center_d = (1/8) * sum_k raw[k][d] * invn[k]
    float cd = 0.f;
#pragma unroll
    for (int k = 0; k < 8; k++) cd += raw[k][tid] * invn[k];
    cd *= 0.125f;
    cen[tid] = cd;

    // hi/lo bf16 split for tensor-core GEMM
    __nv_bfloat16 hb = __float2bfloat16(cd);
    float hf = __bfloat162float(hb);
    g_hi[(size_t)c * DIM + tid] = hb;
    g_lo[(size_t)c * DIM + tid] = __float2bfloat16(cd - hf);

    // ||center||^2 block reduce
    float s2 = cd * cd;
#pragma unroll
    for (int o = 16; o > 0; o >>= 1) s2 += __shfl_xor_sync(0xffffffffu, s2, o);
    if (lane == 0) redA[w] = s2;
    __syncthreads();

    float sqc = 0.f;
#pragma unroll
    for (int k = 0; k < 8; k++) sqc += redA[k];
    if (tid == 0) { g_sq[c] = sqc; g_an[c] = 0.f; }
    float icn = rsqrtf(sqc);

    float dot = 0.f;
#pragma unroll
    for (int j = 0; j < 8; j++) dot += v[j] * cen[lane + 32 * j];
#pragma unroll
    for (int o = 16; o > 0; o >>= 1) dot += __shfl_xor_sync(0xffffffffu, dot, o);
    if (lane == 0) {
        float d = invn[w] * icn * dot;
        redB[w] = sqrtf(fmaxf(2.f - 2.f * d, 0.f));
    }
    __syncthreads();
    if (tid == 0) {
        float p = 0.f;
#pragma unroll
        for (int k = 0; k < 8; k++) p += redB[k];
        g_pc[c] = p;
    }
}

// ---------------------------------------------------------------------------
// Kernel 2: tensor-core Gram GEMM with fused hinge epilogue.
// G = H·H^T + L·H^T  (concat K=512, B side = [H|H]); bf16 mma, fp32 accum.
// Block: 64x64 tile, 128 threads = 4 warps (2x2), each warp 32x32.
// ---------------------------------------------------------------------------
__global__ void __launch_bounds__(128) mma_hinge(int C) {
    __shared__ __align__(16) __nv_bfloat16 As[64][72];  // pitch 72 (144B) kills ldmatrix conflicts
    __shared__ __align__(16) __nv_bfloat16 Bs[64][72];

    int tid  = threadIdx.x;
    int warp = tid >> 5;
    int lane = tid & 31;
    int i0 = blockIdx.y * 64;
    int j0 = blockIdx.x * 64;
    int wr = warp >> 1;   // 0..1
    int wc = warp & 1;    // 0..1

    float acc[2][4][4] = {};   // [mi 16-rows][nj 8-cols][4 c-regs]

    for (int kc = 0; kc < 2 * DIM; kc += 64) {
        const __nv_bfloat16* srcA = (kc < DIM) ? g_hi : g_lo;
        int k0 = kc & (DIM - 1);
        __syncthreads();
#pragma unroll
        for (int vv = 0; vv < 4; vv++) {
            int idx = tid + vv * 128;      // 0..511
            int r = idx >> 3;              // row in tile
            int q = idx & 7;               // 8-bf16 chunk
            uint4 a = *(const uint4*)(srcA + (size_t)(i0 + r) * DIM + k0 + q * 8);
            *(uint4*)&As[r][q * 8] = a;
            uint4 b = *(const uint4*)(g_hi + (size_t)(j0 + r) * DIM + k0 + q * 8);
            *(uint4*)&Bs[r][q * 8] = b;
        }
        __syncthreads();

#pragma unroll
        for (int kk = 0; kk < 64; kk += 16) {
            uint32_t afr[2][4];
#pragma unroll
            for (int mi = 0; mi < 2; mi++) {
                int row = wr * 32 + mi * 16 + (lane & 15);
                int col = kk + (lane >> 4) * 8;
                uint32_t addr = (uint32_t)__cvta_generic_to_shared(&As[row][col]);
                asm volatile("ldmatrix.sync.aligned.m8n8.x4.shared.b16 {%0,%1,%2,%3}, [%4];"
                    : "=r"(afr[mi][0]), "=r"(afr[mi][1]), "=r"(afr[mi][2]), "=r"(afr[mi][3])
                    : "r"(addr));
            }
            uint32_t bfr[4][2];
#pragma unroll
            for (int nq = 0; nq < 2; nq++) {
                int row = wc * 32 + nq * 16 + ((lane >> 3) & 1) * 8 + (lane & 7);
                int col = kk + (lane >> 4) * 8;
                uint32_t addr = (uint32_t)__cvta_generic_to_shared(&Bs[row][col]);
                uint32_t r0, r1, r2, r3;
                asm volatile("ldmatrix.sync.aligned.m8n8.x4.shared.b16 {%0,%1,%2,%3}, [%4];"
                    : "=r"(r0), "=r"(r1), "=r"(r2), "=r"(r3) : "r"(addr));
                bfr[nq * 2 + 0][0] = r0; bfr[nq * 2 + 0][1] = r2;
                bfr[nq * 2 + 1][0] = r1; bfr[nq * 2 + 1][1] = r3;
            }
#pragma unroll
            for (int mi = 0; mi < 2; mi++)
#pragma unroll
                for (int nj = 0; nj < 4; nj++) {
                    asm volatile(
                        "mma.sync.aligned.m16n8k16.row.col.f32.bf16.bf16.f32 "
                        "{%0,%1,%2,%3}, {%4,%5,%6,%7}, {%8,%9}, {%0,%1,%2,%3};"
                        : "+f"(acc[mi][nj][0]), "+f"(acc[mi][nj][1]),
                          "+f"(acc[mi][nj][2]), "+f"(acc[mi][nj][3])
                        : "r"(afr[mi][0]), "r"(afr[mi][1]), "r"(afr[mi][2]), "r"(afr[mi][3]),
                          "r"(bfr[nj][0]), "r"(bfr[nj][1]));
                }
        }
    }

    // Fused hinge epilogue. C-frag layout: c0,c1 = (row=lane>>2, col=(lane&3)*2+{0,1});
    // c2,c3 = row+8.
    int qr = lane >> 2;
    int qc = lane & 3;
#pragma unroll
    for (int mi = 0; mi < 2; mi++) {
#pragma unroll
        for (int h = 0; h < 2; h++) {
            int i = i0 + wr * 32 + mi * 16 + h * 8 + qr;
            float sqi = g_sq[i];
            float s = 0.f;
#pragma unroll
            for (int nj = 0; nj < 4; nj++) {
#pragma unroll
                for (int e = 0; e < 2; e++) {
                    int j = j0 + wc * 32 + nj * 8 + qc * 2 + e;
                    float d2 = sqi + g_sq[j] - 2.f * acc[mi][nj][h * 2 + e];
                    float d  = sqrtf(fmaxf(d2, 1e-12f));
                    float hh = fmaxf(0.7f - d, 0.f);
                    if (i != j) s += hh;
                }
            }
            // reduce over the quad (qc = 0..3 share the row)
            s += __shfl_xor_sync(0xffffffffu, s, 1);
            s += __shfl_xor_sync(0xffffffffu, s, 2);
            if (qc == 0) atomicAdd(&g_an[i], s);
        }
    }
}

// ---------------------------------------------------------------------------
// Kernel 3: final reductions + 3 scalar outputs
// ---------------------------------------------------------------------------
__global__ void __launch_bounds__(256) finalize_kernel(float* __restrict__ out, int n, int C) {
    int tid  = threadIdx.x;
    int w    = tid >> 5;
    int lane = tid & 31;
    __shared__ float sp[8], sa[8];

    float p = 0.f, a = 0.f;
    for (int i = tid; i < C; i += 256) { p += g_pc[i]; a += g_an[i]; }
#pragma unroll
    for (int o = 16; o > 0; o >>= 1) {
        p += __shfl_xor_sync(0xffffffffu, p, o);
        a += __shfl_xor_sync(0xffffffffu, a, o);
    }
    if (lane == 0) { sp[w] = p; sa[w] = a; }
    __syncthreads();
    if (tid == 0) {
        float P = 0.f, A = 0.f;
#pragma unroll
        for (int k = 0; k < 8; k++) { P += sp[k]; A += sa[k]; }
        float pc_mean = P / (float)n;
        float an_mean = A / ((float)(C - 1) * (float)C);
        out[0] = pc_mean + an_mean;
        out[1] = pc_mean;
        out[2] = an_mean;
    }
}

extern "C" void kernel_launch(void* const* d_in, const int* in_sizes, int n_in,
                              void* d_out, int out_size) {
    const float* in = (const float*)d_in[0];
    int n = in_sizes[0] / DIM;   // 8192
    int C = n / KSZ;             // 1024

    centers_kernel<<<C, 256>>>(in);
    dim3 grid(C / 64, C / 64);
    mma_hinge<<<grid, 128>>>(C);
    finalize_kernel<<<1, 256>>>((float*)d_out, n, C);
}